// round 10
// baseline (speedup 1.0000x reference)
#include <cuda_runtime.h>
#include <cstdint>

namespace {

constexpr int KNN  = 32;   // K nearest neighbors
constexpr int IN2  = 64;   // 2K MLP input
constexpr int MID  = 32;   // hidden width of fc2
constexpr int HALF = 16;   // hidden units per thread (2 threads per element)

__device__ __forceinline__ float fast_tanh(float x) {
    float y;
    asm("tanh.approx.f32 %0, %1;" : "=f"(y) : "f"(x));
    return y;
}

__global__ __launch_bounds__(128) void meta_kernel(
    const int*   __restrict__ vals,
    const float* __restrict__ dist,
    const float* __restrict__ w1,   // [64,32]
    const float* __restrict__ b1,   // [32]
    const float* __restrict__ w2,   // [32,2]
    const float* __restrict__ b2,   // [2]
    const float* __restrict__ fw1,  // [2,4]
    const float* __restrict__ fb1,  // [4]
    const float* __restrict__ fw2,  // [4,1]
    const float* __restrict__ fb2,  // [1]
    float* __restrict__ out,        // [n,3]
    int n)
{
    __shared__ __align__(16) float s_w1[IN2 * MID];
    __shared__ __align__(16) float s_b1[MID];
    __shared__ __align__(16) float s_w2[MID * 2];

    {
        const int tid = threadIdx.x;
        for (int i = tid; i < IN2 * MID; i += blockDim.x) s_w1[i] = w1[i];
        if (tid < MID)     s_b1[tid] = b1[tid];
        if (tid < MID * 2) s_w2[tid] = w2[tid];
        __syncthreads();
    }

    const int gt   = blockIdx.x * blockDim.x + threadIdx.x;
    const int e    = gt >> 1;          // element index
    const int half = gt & 1;           // which 16 hidden units this thread owns
    if (e >= n) return;
    const int off  = half * HALF;

    // ---- issue ALL global loads up front: 16 independent LDG.128 in flight ----
    int4   v4[KNN / 4];
    float4 d4[KNN / 4];
    {
        const int4*   vp = reinterpret_cast<const int4*>(vals + (size_t)e * KNN);
        const float4* dp = reinterpret_cast<const float4*>(dist + (size_t)e * KNN);
        #pragma unroll
        for (int c = 0; c < KNN / 4; c++) v4[c] = vp[c];
        #pragma unroll
        for (int c = 0; c < KNN / 4; c++) d4[c] = dp[c];
    }

    // ---- init accumulators with bias slice ----
    float h[HALF];
    #pragma unroll
    for (int j = 0; j < HALF / 4; j++) {
        float4 bb = *reinterpret_cast<const float4*>(s_b1 + off + 4 * j);
        h[4*j+0] = bb.x; h[4*j+1] = bb.y; h[4*j+2] = bb.z; h[4*j+3] = bb.w;
    }

    // ---- phase B: streaming label counts (128-bit seen bitmap), FMA as produced.
    //      Bit 0 pre-set: label 0 is "already seen" -> no separate val!=0 test.
    {
        uint64_t seen_lo = 1ull, seen_hi = 0ull;
        int cnt = 0;
        #pragma unroll
        for (int c = 0; c < KNN / 4; c++) {
            const int4 t = v4[c];
            const int vv[4] = {t.x, t.y, t.z, t.w};
            #pragma unroll
            for (int r = 0; r < 4; r++) {
                const int k = 4 * c + r;
                const int val = vv[r];
                const uint64_t m  = 1ull << (val & 63);
                const bool     hi = val >= 64;
                const uint64_t w  = hi ? seen_hi : seen_lo;
                const bool isnew  = (w & m) == 0ull;
                if (hi) seen_hi |= m; else seen_lo |= m;
                cnt += isnew ? 1 : 0;
                const float cfk = (float)cnt;

                const float* wr = s_w1 + (KNN + k) * MID + off;
                #pragma unroll
                for (int j = 0; j < HALF / 4; j++) {
                    float4 w4 = *reinterpret_cast<const float4*>(wr + 4 * j);
                    h[4*j+0] = fmaf(cfk, w4.x, h[4*j+0]);
                    h[4*j+1] = fmaf(cfk, w4.y, h[4*j+1]);
                    h[4*j+2] = fmaf(cfk, w4.z, h[4*j+2]);
                    h[4*j+3] = fmaf(cfk, w4.w, h[4*j+3]);
                }
            }
        }
    }

    // ---- phase A: distance features (rows 0..31), consuming held float4s ----
    #pragma unroll
    for (int c = 0; c < KNN / 4; c++) {
        const float4 t = d4[c];
        const float xv[4] = {t.x, t.y, t.z, t.w};
        #pragma unroll
        for (int r = 0; r < 4; r++) {
            const float xi = xv[r];
            const float* wr = s_w1 + (4 * c + r) * MID + off;
            #pragma unroll
            for (int j = 0; j < HALF / 4; j++) {
                float4 w4 = *reinterpret_cast<const float4*>(wr + 4 * j);
                h[4*j+0] = fmaf(xi, w4.x, h[4*j+0]);
                h[4*j+1] = fmaf(xi, w4.y, h[4*j+1]);
                h[4*j+2] = fmaf(xi, w4.z, h[4*j+2]);
                h[4*j+3] = fmaf(xi, w4.w, h[4*j+3]);
            }
        }
    }

    // ---- fc2 layer 2: partial sums over this thread's 16 hidden units ----
    float p0 = 0.f, p1 = 0.f;
    #pragma unroll
    for (int j = 0; j < HALF; j++) {
        const float t = fast_tanh(h[j]);
        p0 = fmaf(t, s_w2[2 * (off + j) + 0], p0);
        p1 = fmaf(t, s_w2[2 * (off + j) + 1], p1);
    }
    p0 += __shfl_xor_sync(0xffffffffu, p0, 1);
    p1 += __shfl_xor_sync(0xffffffffu, p1, 1);

    // ---- fc1 + store (even thread of the pair only) ----
    if (half == 0) {
        const float o0 = p0 + b2[0];
        const float o1 = p1 + b2[1];
        float o2 = fb2[0];
        #pragma unroll
        for (int m = 0; m < 4; m++) {
            const float t = fast_tanh(fb1[m] + fmaf(o0, fw1[m], o1 * fw1[4 + m]));
            o2 = fmaf(t, fw2[m], o2);
        }
        out[3*e+0] = o0;
        out[3*e+1] = o1;
        out[3*e+2] = o2;
    }
}

} // anonymous namespace

extern "C" void kernel_launch(void* const* d_in, const int* in_sizes, int n_in,
                              void* d_out, int out_size) {
    const int*   vals = (const int*)  d_in[0];
    const float* dist = (const float*)d_in[1];
    const float* w1   = (const float*)d_in[2];
    const float* b1   = (const float*)d_in[3];
    const float* w2   = (const float*)d_in[4];
    const float* b2   = (const float*)d_in[5];
    const float* fw1  = (const float*)d_in[6];
    const float* fb1  = (const float*)d_in[7];
    const float* fw2  = (const float*)d_in[8];
    const float* fb2  = (const float*)d_in[9];
    float* out = (float*)d_out;

    const int n = in_sizes[0] / KNN;        // B*S elements
    const int total = 2 * n;                // 2 threads per element
    const int threads = 128;
    const int blocks = (total + threads - 1) / threads;
    meta_kernel<<<blocks, threads>>>(vals, dist, w1, b1, w2, b2,
                                     fw1, fb1, fw2, fb2, out, n);
}

// round 11
// speedup vs baseline: 1.0663x; 1.0663x over previous
#include <cuda_runtime.h>
#include <cstdint>

namespace {

constexpr int KNN  = 32;   // K nearest neighbors
constexpr int IN2  = 64;   // 2K MLP input
constexpr int MID  = 32;   // hidden width of fc2
constexpr int HALF = 16;   // hidden units per thread (2 threads per element)
constexpr int TPB  = 64;   // small blocks -> 1024 CTAs -> better SM balance

__device__ __forceinline__ float fast_tanh(float x) {
    float y;
    asm("tanh.approx.f32 %0, %1;" : "=f"(y) : "f"(x));
    return y;
}

// minBlocksPerMultiprocessor = 8 -> ptxas reg budget 65536/(64*8) = 128 regs,
// removing the ~56-reg cap (and its spills) seen in every previous round.
__global__ __launch_bounds__(TPB, 8) void meta_kernel(
    const int*   __restrict__ vals,
    const float* __restrict__ dist,
    const float* __restrict__ w1,   // [64,32]
    const float* __restrict__ b1,   // [32]
    const float* __restrict__ w2,   // [32,2]
    const float* __restrict__ b2,   // [2]
    const float* __restrict__ fw1,  // [2,4]
    const float* __restrict__ fb1,  // [4]
    const float* __restrict__ fw2,  // [4,1]
    const float* __restrict__ fb2,  // [1]
    float* __restrict__ out,        // [n,3]
    int n)
{
    __shared__ __align__(16) float s_w1[IN2 * MID];
    __shared__ __align__(16) float s_b1[MID];
    __shared__ __align__(16) float s_w2[MID * 2];

    {
        const int tid = threadIdx.x;
        #pragma unroll
        for (int i = 0; i < (IN2 * MID) / TPB; i++) s_w1[tid + i * TPB] = w1[tid + i * TPB];
        if (tid < MID)     s_b1[tid] = b1[tid];
        if (tid < MID * 2) s_w2[tid] = w2[tid];
        __syncthreads();
    }

    const int gt   = blockIdx.x * TPB + threadIdx.x;
    const int e    = gt >> 1;          // element index
    const int half = gt & 1;           // which 16 hidden units this thread owns
    if (e >= n) return;
    const int off  = half * HALF;

    // ---- issue ALL global loads up front: 16 independent LDG.128 in flight ----
    int4   v4[KNN / 4];
    float4 d4[KNN / 4];
    {
        const int4*   vp = reinterpret_cast<const int4*>(vals + (size_t)e * KNN);
        const float4* dp = reinterpret_cast<const float4*>(dist + (size_t)e * KNN);
        #pragma unroll
        for (int c = 0; c < KNN / 4; c++) v4[c] = vp[c];
        #pragma unroll
        for (int c = 0; c < KNN / 4; c++) d4[c] = dp[c];
    }

    // ---- init accumulators with bias slice ----
    float h[HALF];
    #pragma unroll
    for (int j = 0; j < HALF / 4; j++) {
        float4 bb = *reinterpret_cast<const float4*>(s_b1 + off + 4 * j);
        h[4*j+0] = bb.x; h[4*j+1] = bb.y; h[4*j+2] = bb.z; h[4*j+3] = bb.w;
    }

    // ---- phase B: streaming label counts (128-bit seen bitmap), FMA as produced.
    //      Bit 0 pre-set: label 0 is "already seen" -> no separate val!=0 test.
    {
        uint64_t seen_lo = 1ull, seen_hi = 0ull;
        int cnt = 0;
        #pragma unroll
        for (int c = 0; c < KNN / 4; c++) {
            const int4 t = v4[c];
            const int vv[4] = {t.x, t.y, t.z, t.w};
            #pragma unroll
            for (int r = 0; r < 4; r++) {
                const int k = 4 * c + r;
                const int val = vv[r];
                const uint64_t m  = 1ull << (val & 63);
                const bool     hi = val >= 64;
                const uint64_t w  = hi ? seen_hi : seen_lo;
                const bool isnew  = (w & m) == 0ull;
                if (hi) seen_hi |= m; else seen_lo |= m;
                cnt += isnew ? 1 : 0;
                const float cfk = (float)cnt;

                const float* wr = s_w1 + (KNN + k) * MID + off;
                #pragma unroll
                for (int j = 0; j < HALF / 4; j++) {
                    float4 w4 = *reinterpret_cast<const float4*>(wr + 4 * j);
                    h[4*j+0] = fmaf(cfk, w4.x, h[4*j+0]);
                    h[4*j+1] = fmaf(cfk, w4.y, h[4*j+1]);
                    h[4*j+2] = fmaf(cfk, w4.z, h[4*j+2]);
                    h[4*j+3] = fmaf(cfk, w4.w, h[4*j+3]);
                }
            }
        }
    }

    // ---- phase A: distance features (rows 0..31), consuming held float4s ----
    #pragma unroll
    for (int c = 0; c < KNN / 4; c++) {
        const float4 t = d4[c];
        const float xv[4] = {t.x, t.y, t.z, t.w};
        #pragma unroll
        for (int r = 0; r < 4; r++) {
            const float xi = xv[r];
            const float* wr = s_w1 + (4 * c + r) * MID + off;
            #pragma unroll
            for (int j = 0; j < HALF / 4; j++) {
                float4 w4 = *reinterpret_cast<const float4*>(wr + 4 * j);
                h[4*j+0] = fmaf(xi, w4.x, h[4*j+0]);
                h[4*j+1] = fmaf(xi, w4.y, h[4*j+1]);
                h[4*j+2] = fmaf(xi, w4.z, h[4*j+2]);
                h[4*j+3] = fmaf(xi, w4.w, h[4*j+3]);
            }
        }
    }

    // ---- fc2 layer 2: partial sums over this thread's 16 hidden units ----
    float p0 = 0.f, p1 = 0.f;
    #pragma unroll
    for (int j = 0; j < HALF; j++) {
        const float t = fast_tanh(h[j]);
        p0 = fmaf(t, s_w2[2 * (off + j) + 0], p0);
        p1 = fmaf(t, s_w2[2 * (off + j) + 1], p1);
    }
    p0 += __shfl_xor_sync(0xffffffffu, p0, 1);
    p1 += __shfl_xor_sync(0xffffffffu, p1, 1);

    // ---- fc1 + store (even thread of the pair only) ----
    if (half == 0) {
        const float o0 = p0 + b2[0];
        const float o1 = p1 + b2[1];
        float o2 = fb2[0];
        #pragma unroll
        for (int m = 0; m < 4; m++) {
            const float t = fast_tanh(fb1[m] + fmaf(o0, fw1[m], o1 * fw1[4 + m]));
            o2 = fmaf(t, fw2[m], o2);
        }
        out[3*e+0] = o0;
        out[3*e+1] = o1;
        out[3*e+2] = o2;
    }
}

} // anonymous namespace

extern "C" void kernel_launch(void* const* d_in, const int* in_sizes, int n_in,
                              void* d_out, int out_size) {
    const int*   vals = (const int*)  d_in[0];
    const float* dist = (const float*)d_in[1];
    const float* w1   = (const float*)d_in[2];
    const float* b1   = (const float*)d_in[3];
    const float* w2   = (const float*)d_in[4];
    const float* b2   = (const float*)d_in[5];
    const float* fw1  = (const float*)d_in[6];
    const float* fb1  = (const float*)d_in[7];
    const float* fw2  = (const float*)d_in[8];
    const float* fb2  = (const float*)d_in[9];
    float* out = (float*)d_out;

    const int n = in_sizes[0] / KNN;        // B*S elements
    const int total = 2 * n;                // 2 threads per element
    const int blocks = (total + TPB - 1) / TPB;
    meta_kernel<<<blocks, TPB>>>(vals, dist, w1, b1, w2, b2,
                                 fw1, fb1, fw2, fb2, out, n);
}

// round 13
// speedup vs baseline: 1.0850x; 1.0175x over previous
#include <cuda_runtime.h>
#include <cstdint>

namespace {

constexpr int KNN  = 32;   // K nearest neighbors
constexpr int IN2  = 64;   // 2K MLP input
constexpr int MID  = 32;   // hidden width of fc2
constexpr int HALF = 16;   // hidden units per thread (2 threads per element)
constexpr int TPB  = 64;

__device__ __forceinline__ float fast_tanh(float x) {
    float y;
    asm("tanh.approx.f32 %0, %1;" : "=f"(y) : "f"(x));
    return y;
}

__device__ __forceinline__ unsigned long long pack2(float x) {
    unsigned long long r;
    asm("mov.b64 %0, {%1, %1};" : "=l"(r) : "f"(x));
    return r;
}
__device__ __forceinline__ void ffma2(unsigned long long& d,
                                      unsigned long long a,
                                      unsigned long long b) {
    asm("fma.rn.f32x2 %0, %1, %2, %0;" : "+l"(d) : "l"(a), "l"(b));
}
__device__ __forceinline__ void unpack2(unsigned long long p, float& lo, float& hi) {
    asm("mov.b64 {%0, %1}, %2;" : "=f"(lo), "=f"(hi) : "l"(p));
}

__global__ __launch_bounds__(TPB, 8) void meta_kernel(
    const int*   __restrict__ vals,
    const float* __restrict__ dist,
    const float* __restrict__ w1,   // [64,32]
    const float* __restrict__ b1,   // [32]
    const float* __restrict__ w2,   // [32,2]
    const float* __restrict__ b2,   // [2]
    const float* __restrict__ fw1,  // [2,4]
    const float* __restrict__ fb1,  // [4]
    const float* __restrict__ fw2,  // [4,1]
    const float* __restrict__ fb2,  // [1]
    float* __restrict__ out,        // [n,3]
    int n)
{
    __shared__ __align__(16) float s_w1[IN2 * MID];
    __shared__ __align__(16) float s_b1[MID];
    __shared__ __align__(16) float s_w2[MID * 2];

    {
        const int tid = threadIdx.x;
        #pragma unroll
        for (int i = 0; i < (IN2 * MID) / TPB; i++) s_w1[tid + i * TPB] = w1[tid + i * TPB];
        if (tid < MID)     s_b1[tid] = b1[tid];
        if (tid < MID * 2) s_w2[tid] = w2[tid];
        __syncthreads();
    }

    const int gt   = blockIdx.x * TPB + threadIdx.x;
    const int e    = gt >> 1;          // element index
    const int half = gt & 1;           // hidden-unit half AND bitmap word owner
    if (e >= n) return;
    const int off  = half * HALF;

    // ---- issue ALL global loads up front ----
    int4   v4[KNN / 4];
    float4 d4[KNN / 4];
    {
        const int4*   vp = reinterpret_cast<const int4*>(vals + (size_t)e * KNN);
        const float4* dp = reinterpret_cast<const float4*>(dist + (size_t)e * KNN);
        #pragma unroll
        for (int c = 0; c < KNN / 4; c++) v4[c] = vp[c];
        #pragma unroll
        for (int c = 0; c < KNN / 4; c++) d4[c] = dp[c];
    }

    // ---- split bitmap: even lane owns labels [0,64), odd lane [64,128).
    //      flags bit k = "v[k] is a first-occurring nonzero label".
    unsigned flags = 0u;
    {
        // even lane pre-seeds bit 0 so label 0 never counts
        uint64_t seen = (half == 0) ? 1ull : 0ull;
        const bool want_hi = (half == 1);
        #pragma unroll
        for (int c = 0; c < KNN / 4; c++) {
            const int4 t = v4[c];
            const int vv[4] = {t.x, t.y, t.z, t.w};
            #pragma unroll
            for (int r = 0; r < 4; r++) {
                const int k   = 4 * c + r;
                const int val = vv[r];
                const bool mine = ((val >= 64) == want_hi);
                const uint64_t m = 1ull << (val & 63);
                const bool isnew = mine && ((seen & m) == 0ull);
                if (mine) seen |= m;
                flags |= isnew ? (1u << k) : 0u;
            }
        }
        flags |= __shfl_xor_sync(0xffffffffu, flags, 1);
    }

    // ---- init packed accumulators with bias slice (8 x f32x2 = 16 units) ----
    unsigned long long h2[HALF / 2];
    {
        const ulonglong2* bp = reinterpret_cast<const ulonglong2*>(s_b1 + off);
        #pragma unroll
        for (int q = 0; q < HALF / 4; q++) {
            ulonglong2 t = bp[q];
            h2[2*q+0] = t.x;
            h2[2*q+1] = t.y;
        }
    }

    // ---- phase B: label-count features (rows 32..63), counts via popc prefix ----
    #pragma unroll
    for (int k = 0; k < KNN; k++) {
        const float cfk = (float)__popc(flags << (31 - k));
        const unsigned long long cc = pack2(cfk);
        const ulonglong2* wr = reinterpret_cast<const ulonglong2*>(
            s_w1 + (KNN + k) * MID + off);
        #pragma unroll
        for (int q = 0; q < HALF / 4; q++) {
            ulonglong2 w = wr[q];
            ffma2(h2[2*q+0], cc, w.x);
            ffma2(h2[2*q+1], cc, w.y);
        }
    }

    // ---- phase A: distance features (rows 0..31) ----
    #pragma unroll
    for (int c = 0; c < KNN / 4; c++) {
        const float4 t = d4[c];
        const float xv[4] = {t.x, t.y, t.z, t.w};
        #pragma unroll
        for (int r = 0; r < 4; r++) {
            const unsigned long long xx = pack2(xv[r]);
            const ulonglong2* wr = reinterpret_cast<const ulonglong2*>(
                s_w1 + (4 * c + r) * MID + off);
            #pragma unroll
            for (int q = 0; q < HALF / 4; q++) {
                ulonglong2 w = wr[q];
                ffma2(h2[2*q+0], xx, w.x);
                ffma2(h2[2*q+1], xx, w.y);
            }
        }
    }

    // ---- fc2 layer 2: partial sums over this thread's 16 hidden units ----
    float p0 = 0.f, p1 = 0.f;
    #pragma unroll
    for (int q = 0; q < HALF / 2; q++) {
        float a, b;
        unpack2(h2[q], a, b);
        const float ta = fast_tanh(a);
        const float tb = fast_tanh(b);
        const int j = 2 * q;
        p0 = fmaf(ta, s_w2[2 * (off + j) + 0], p0);
        p1 = fmaf(ta, s_w2[2 * (off + j) + 1], p1);
        p0 = fmaf(tb, s_w2[2 * (off + j + 1) + 0], p0);
        p1 = fmaf(tb, s_w2[2 * (off + j + 1) + 1], p1);
    }
    p0 += __shfl_xor_sync(0xffffffffu, p0, 1);
    p1 += __shfl_xor_sync(0xffffffffu, p1, 1);

    // ---- fc1 + store (even thread of the pair only) ----
    if (half == 0) {
        const float o0 = p0 + b2[0];
        const float o1 = p1 + b2[1];
        float o2 = fb2[0];
        #pragma unroll
        for (int m = 0; m < 4; m++) {
            const float t = fast_tanh(fb1[m] + fmaf(o0, fw1[m], o1 * fw1[4 + m]));
            o2 = fmaf(t, fw2[m], o2);
        }
        out[3*e+0] = o0;
        out[3*e+1] = o1;
        out[3*e+2] = o2;
    }
}

} // anonymous namespace

extern "C" void kernel_launch(void* const* d_in, const int* in_sizes, int n_in,
                              void* d_out, int out_size) {
    const int*   vals = (const int*)  d_in[0];
    const float* dist = (const float*)d_in[1];
    const float* w1   = (const float*)d_in[2];
    const float* b1   = (const float*)d_in[3];
    const float* w2   = (const float*)d_in[4];
    const float* b2   = (const float*)d_in[5];
    const float* fw1  = (const float*)d_in[6];
    const float* fb1  = (const float*)d_in[7];
    const float* fw2  = (const float*)d_in[8];
    const float* fb2  = (const float*)d_in[9];
    float* out = (float*)d_out;

    const int n = in_sizes[0] / KNN;        // B*S elements
    const int total = 2 * n;                // 2 threads per element
    const int blocks = (total + TPB - 1) / TPB;
    meta_kernel<<<blocks, TPB>>>(vals, dist, w1, b1, w2, b2,
                                 fw1, fb1, fw2, fb2, out, n);
}

// round 14
// speedup vs baseline: 1.2955x; 1.1940x over previous
#include <cuda_runtime.h>
#include <cstdint>

namespace {

constexpr int KNN  = 32;   // K nearest neighbors
constexpr int IN2  = 64;   // 2K MLP input
constexpr int MID  = 32;   // hidden width of fc2
constexpr int HALF = 16;   // hidden units per thread (pair splits 32 cols)
constexpr int TPB  = 64;

__device__ __forceinline__ float fast_tanh(float x) {
    float y;
    asm("tanh.approx.f32 %0, %1;" : "=f"(y) : "f"(x));
    return y;
}
__device__ __forceinline__ unsigned long long pack2(float x) {
    unsigned long long r;
    asm("mov.b64 %0, {%1, %1};" : "=l"(r) : "f"(x));
    return r;
}
__device__ __forceinline__ void ffma2(unsigned long long& d,
                                      unsigned long long a,
                                      unsigned long long b) {
    asm("fma.rn.f32x2 %0, %1, %2, %0;" : "+l"(d) : "l"(a), "l"(b));
}
__device__ __forceinline__ void unpack2(unsigned long long p, float& lo, float& hi) {
    asm("mov.b64 {%0, %1}, %2;" : "=f"(lo), "=f"(hi) : "l"(p));
}

// grid is 512 CTAs -> <=4 resident CTAs/SM; declare that so ptxas gets a
// 255-reg budget (no spills; the 2-element live set peaks ~115 regs).
__global__ __launch_bounds__(TPB, 4) void meta_kernel(
    const int*   __restrict__ vals,
    const float* __restrict__ dist,
    const float* __restrict__ w1,   // [64,32]
    const float* __restrict__ b1,   // [32]
    const float* __restrict__ w2,   // [32,2]
    const float* __restrict__ b2,   // [2]
    const float* __restrict__ fw1,  // [2,4]
    const float* __restrict__ fb1,  // [4]
    const float* __restrict__ fw2,  // [4,1]
    const float* __restrict__ fb2,  // [1]
    float* __restrict__ out,        // [n,3]
    int n)
{
    __shared__ __align__(16) float s_w1[IN2 * MID];
    __shared__ __align__(16) float s_b1[MID];
    __shared__ __align__(16) float s_w2[MID * 2];

    {
        const int tid = threadIdx.x;
        #pragma unroll
        for (int i = 0; i < (IN2 * MID) / TPB; i++) s_w1[tid + i * TPB] = w1[tid + i * TPB];
        if (tid < MID)     s_b1[tid] = b1[tid];
        if (tid < MID * 2) s_w2[tid] = w2[tid];
        __syncthreads();
    }

    const int gt   = blockIdx.x * TPB + threadIdx.x;
    const int pair = gt >> 1;          // lane pair index
    const int half = gt & 1;           // column half AND bitmap word owner
    const int e0   = 2 * pair;         // this thread pair handles elements e0,e1
    const int e1   = e0 + 1;
    if (e1 >= n) return;               // n is even for this problem
    const int off  = half * HALF;

    // ---- stage 1: label loads for both elements (16 LDG.128 in flight) ----
    int4 v0[KNN / 4], v1[KNN / 4];
    {
        const int4* vp0 = reinterpret_cast<const int4*>(vals + (size_t)e0 * KNN);
        const int4* vp1 = reinterpret_cast<const int4*>(vals + (size_t)e1 * KNN);
        #pragma unroll
        for (int c = 0; c < KNN / 4; c++) v0[c] = vp0[c];
        #pragma unroll
        for (int c = 0; c < KNN / 4; c++) v1[c] = vp1[c];
    }

    // ---- split bitmaps: even lane owns labels [0,64), odd lane [64,128) ----
    unsigned flags0 = 0u, flags1 = 0u;
    {
        const bool want_hi = (half == 1);
        uint64_t seen0 = want_hi ? 0ull : 1ull;   // bit0 preseed kills label 0
        uint64_t seen1 = seen0;
        #pragma unroll
        for (int c = 0; c < KNN / 4; c++) {
            const int4 a = v0[c];
            const int4 b = v1[c];
            const int va[4] = {a.x, a.y, a.z, a.w};
            const int vb[4] = {b.x, b.y, b.z, b.w};
            #pragma unroll
            for (int r = 0; r < 4; r++) {
                const int k = 4 * c + r;
                {
                    const int val = va[r];
                    const bool mine = ((val >= 64) == want_hi);
                    const uint64_t m = 1ull << (val & 63);
                    const bool isnew = mine && ((seen0 & m) == 0ull);
                    if (mine) seen0 |= m;
                    flags0 |= isnew ? (1u << k) : 0u;
                }
                {
                    const int val = vb[r];
                    const bool mine = ((val >= 64) == want_hi);
                    const uint64_t m = 1ull << (val & 63);
                    const bool isnew = mine && ((seen1 & m) == 0ull);
                    if (mine) seen1 |= m;
                    flags1 |= isnew ? (1u << k) : 0u;
                }
            }
        }
        flags0 |= __shfl_xor_sync(0xffffffffu, flags0, 1);
        flags1 |= __shfl_xor_sync(0xffffffffu, flags1, 1);
    }

    // ---- stage 2: distance loads (latency hides behind phase B) ----
    float4 d0[KNN / 4], d1[KNN / 4];
    {
        const float4* dp0 = reinterpret_cast<const float4*>(dist + (size_t)e0 * KNN);
        const float4* dp1 = reinterpret_cast<const float4*>(dist + (size_t)e1 * KNN);
        #pragma unroll
        for (int c = 0; c < KNN / 4; c++) d0[c] = dp0[c];
        #pragma unroll
        for (int c = 0; c < KNN / 4; c++) d1[c] = dp1[c];
    }

    // ---- init packed accumulators (both elements) with bias slice ----
    unsigned long long h0[HALF / 2], h1[HALF / 2];
    {
        const ulonglong2* bp = reinterpret_cast<const ulonglong2*>(s_b1 + off);
        #pragma unroll
        for (int q = 0; q < HALF / 4; q++) {
            ulonglong2 t = bp[q];
            h0[2*q+0] = t.x; h0[2*q+1] = t.y;
            h1[2*q+0] = t.x; h1[2*q+1] = t.y;
        }
    }

    // ---- phase B: label-count features; each weight load feeds BOTH elements ----
    #pragma unroll
    for (int k = 0; k < KNN; k++) {
        const unsigned long long cc0 = pack2((float)__popc(flags0 << (31 - k)));
        const unsigned long long cc1 = pack2((float)__popc(flags1 << (31 - k)));
        const ulonglong2* wr = reinterpret_cast<const ulonglong2*>(
            s_w1 + (KNN + k) * MID + off);
        #pragma unroll
        for (int q = 0; q < HALF / 4; q++) {
            ulonglong2 w = wr[q];
            ffma2(h0[2*q+0], cc0, w.x);
            ffma2(h0[2*q+1], cc0, w.y);
            ffma2(h1[2*q+0], cc1, w.x);
            ffma2(h1[2*q+1], cc1, w.y);
        }
    }

    // ---- phase A: distance features; shared weight loads again ----
    #pragma unroll
    for (int c = 0; c < KNN / 4; c++) {
        const float4 ta = d0[c];
        const float4 tb = d1[c];
        const float xa[4] = {ta.x, ta.y, ta.z, ta.w};
        const float xb[4] = {tb.x, tb.y, tb.z, tb.w};
        #pragma unroll
        for (int r = 0; r < 4; r++) {
            const unsigned long long xx0 = pack2(xa[r]);
            const unsigned long long xx1 = pack2(xb[r]);
            const ulonglong2* wr = reinterpret_cast<const ulonglong2*>(
                s_w1 + (4 * c + r) * MID + off);
            #pragma unroll
            for (int q = 0; q < HALF / 4; q++) {
                ulonglong2 w = wr[q];
                ffma2(h0[2*q+0], xx0, w.x);
                ffma2(h0[2*q+1], xx0, w.y);
                ffma2(h1[2*q+0], xx1, w.x);
                ffma2(h1[2*q+1], xx1, w.y);
            }
        }
    }

    // ---- fc2 layer 2: partials for both elements over this thread's 16 cols ----
    float p00 = 0.f, p01 = 0.f, p10 = 0.f, p11 = 0.f;
    #pragma unroll
    for (int q = 0; q < HALF / 2; q++) {
        const int j = 2 * q;
        const float w2a0 = s_w2[2 * (off + j) + 0];
        const float w2a1 = s_w2[2 * (off + j) + 1];
        const float w2b0 = s_w2[2 * (off + j + 1) + 0];
        const float w2b1 = s_w2[2 * (off + j + 1) + 1];
        float a, b;
        unpack2(h0[q], a, b);
        {
            const float tA = fast_tanh(a), tB = fast_tanh(b);
            p00 = fmaf(tA, w2a0, p00); p01 = fmaf(tA, w2a1, p01);
            p00 = fmaf(tB, w2b0, p00); p01 = fmaf(tB, w2b1, p01);
        }
        unpack2(h1[q], a, b);
        {
            const float tA = fast_tanh(a), tB = fast_tanh(b);
            p10 = fmaf(tA, w2a0, p10); p11 = fmaf(tA, w2a1, p11);
            p10 = fmaf(tB, w2b0, p10); p11 = fmaf(tB, w2b1, p11);
        }
    }
    p00 += __shfl_xor_sync(0xffffffffu, p00, 1);
    p01 += __shfl_xor_sync(0xffffffffu, p01, 1);
    p10 += __shfl_xor_sync(0xffffffffu, p10, 1);
    p11 += __shfl_xor_sync(0xffffffffu, p11, 1);

    // ---- fc1 + stores (even lane of the pair only) ----
    if (half == 0) {
        const float fb10 = fb1[0], fb11 = fb1[1], fb12 = fb1[2], fb13 = fb1[3];
        const float fbv[4] = {fb10, fb11, fb12, fb13};
        const float b20 = b2[0], b21 = b2[1];

        const float o00 = p00 + b20, o01 = p01 + b21;
        const float o10 = p10 + b20, o11 = p11 + b21;

        float o02 = fb2[0], o12 = o02;
        #pragma unroll
        for (int m = 0; m < 4; m++) {
            const float w1a = fw1[m], w1b = fw1[4 + m], w2m = fw2[m];
            const float t0 = fast_tanh(fbv[m] + fmaf(o00, w1a, o01 * w1b));
            const float t1 = fast_tanh(fbv[m] + fmaf(o10, w1a, o11 * w1b));
            o02 = fmaf(t0, w2m, o02);
            o12 = fmaf(t1, w2m, o12);
        }
        out[3*e0+0] = o00; out[3*e0+1] = o01; out[3*e0+2] = o02;
        out[3*e1+0] = o10; out[3*e1+1] = o11; out[3*e1+2] = o12;
    }
}

} // anonymous namespace

extern "C" void kernel_launch(void* const* d_in, const int* in_sizes, int n_in,
                              void* d_out, int out_size) {
    const int*   vals = (const int*)  d_in[0];
    const float* dist = (const float*)d_in[1];
    const float* w1   = (const float*)d_in[2];
    const float* b1   = (const float*)d_in[3];
    const float* w2   = (const float*)d_in[4];
    const float* b2   = (const float*)d_in[5];
    const float* fw1  = (const float*)d_in[6];
    const float* fb1  = (const float*)d_in[7];
    const float* fw2  = (const float*)d_in[8];
    const float* fb2  = (const float*)d_in[9];
    float* out = (float*)d_out;

    const int n = in_sizes[0] / KNN;        // B*S elements (even)
    const int total = n;                    // 1 thread per 2 elements... x2 lanes: n threads
    const int blocks = (total + TPB - 1) / TPB;
    meta_kernel<<<blocks, TPB>>>(vals, dist, w1, b1, w2, b2,
                                 fw1, fb1, fw2, fb2, out, n);
}